// round 16
// baseline (speedup 1.0000x reference)
#include <cuda_runtime.h>
#include <cuda_fp16.h>
#include <cstdint>

typedef unsigned long long u64;
typedef unsigned int u32;

// ---------------- problem constants ----------------
constexpr int NB = 4, NC = 256, NO = 256;
constexpr int IH = 64, IW = 64, OH = 128, OW = 128;
constexpr size_t NELEM = (size_t)NB * NC * OH * OW;   // 16,777,216

// Stage buffer: A halo tile [130 rows (x-1..x+128)][128 c] fp16, pitch 256B = 33792 B (pad 132).
constexpr u32 STAGE_BYTES = 33792;
constexpr u32 SMEM_BYTES = 2 * STAGE_BYTES;           // 67,584

// ---------------- device scratch ----------------
__device__ __align__(128) __half g_xh[NELEM];                // NHWC fp16 upsampled x
__device__ __align__(128) __half g_y1h[NELEM];               // NHWC fp16 y1
// B in mma fragment layout: [bt][ck(16)][ntile(16)][lane(32)] -> uint4
__device__ __align__(16) u32 g_Bf1[36 * 16 * 16 * 128];      // 1,179,648 u32
__device__ __align__(16) u32 g_Bf2[40 * 16 * 16 * 128];      // 1,310,720 u32
__device__ float g_s1[NB * NC], g_s2[NB * NC];
__device__ float g_d1[NB * NO], g_d2[NB * NO];

// ---------------- helpers ----------------
__device__ __forceinline__ u32 smem_u32(const void* p) {
    u32 a;
    asm("{ .reg .u64 t; cvta.to.shared.u64 t, %1; cvt.u32.u64 %0, t; }" : "=r"(a) : "l"(p));
    return a;
}
__device__ __forceinline__ void ldsm4(u32* r, u32 addr) {
    asm volatile("ldmatrix.sync.aligned.m8n8.x4.shared.b16 {%0,%1,%2,%3}, [%4];"
                 : "=r"(r[0]), "=r"(r[1]), "=r"(r[2]), "=r"(r[3]) : "r"(addr));
}
__device__ __forceinline__ void mma16816(float* d, const u32* a, u32 b0, u32 b1) {
    asm volatile("mma.sync.aligned.m16n8k16.row.col.f32.f16.f16.f32 "
                 "{%0,%1,%2,%3}, {%4,%5,%6,%7}, {%8,%9}, {%0,%1,%2,%3};"
                 : "+f"(d[0]), "+f"(d[1]), "+f"(d[2]), "+f"(d[3])
                 : "r"(a[0]), "r"(a[1]), "r"(a[2]), "r"(a[3]), "r"(b0), "r"(b1));
}
__device__ __forceinline__ void cp16(u32 dst, const void* src, u32 sz) {
    asm volatile("cp.async.cg.shared.global [%0], [%1], 16, %2;"
                 :: "r"(dst), "l"(src), "r"(sz) : "memory");
}

// ---------------- 1) fused NCHW fp32 -> bilinear 2x upsample -> NHWC fp16 ----------------
__global__ __launch_bounds__(256) void k_upfuse(const float* __restrict__ x) {
    __shared__ float tile[2][32][73];
    const int yo = blockIdx.x, b = blockIdx.y;
    const int t = threadIdx.x;

    int y0; float fy;
    if (yo & 1) { y0 = yo >> 1;       fy = 0.25f; }
    else        { y0 = (yo >> 1) - 1; fy = 0.75f; }
    const int y1c = min(y0 + 1, IH - 1);
    const int y0c = max(y0, 0);

    for (int c0 = 0; c0 < 256; c0 += 32) {
        __syncthreads();
#pragma unroll
        for (int k = 0; k < 16; ++k) {
            int idx = k * 256 + t;
            int xs = idx & 63, c = (idx >> 6) & 31, yq = idx >> 11;
            int ys = yq ? y1c : y0c;
            tile[yq][c][xs] = x[((size_t)(b * 256 + c0 + c) * 64 + ys) * 64 + xs];
        }
        __syncthreads();
#pragma unroll
        for (int k = 0; k < 8; ++k) {
            int pos = k * 256 + t;
            int c2 = pos & 15, xo = pos >> 4;
            int x0; float fx;
            if (xo & 1) { x0 = xo >> 1;       fx = 0.25f; }
            else        { x0 = (xo >> 1) - 1; fx = 0.75f; }
            int x1c = min(x0 + 1, IW - 1);
            int x0c = max(x0, 0);
            u32 outv = 0;
#pragma unroll
            for (int h = 0; h < 2; ++h) {
                int c = c2 * 2 + h;
                float v00 = tile[0][c][x0c], v01 = tile[0][c][x1c];
                float v10 = tile[1][c][x0c], v11 = tile[1][c][x1c];
                float vt = v00 + fx * (v01 - v00);
                float vb = v10 + fx * (v11 - v10);
                u32 hb = (u32)__half_as_ushort(__float2half(vt + fy * (vb - vt)));
                outv |= hb << (16 * h);
            }
            *(u32*)(g_xh + ((size_t)(b * 128 + yo) * 128 + xo) * 256 + c0 + c2 * 2) = outv;
        }
    }
}

// ---------------- 2) styles ----------------
__global__ void k_styles(const float* __restrict__ istyle,
                         const float* __restrict__ w1, const float* __restrict__ b1,
                         const float* __restrict__ w2, const float* __restrict__ b2) {
    int b = blockIdx.x & 3;
    int which = blockIdx.x >> 2;
    int c = threadIdx.x;
    const float* wrow = (which ? w2 : w1) + (size_t)c * 256;
    const float* ist = istyle + b * 256;
    float acc = (which ? b2 : b1)[c];
#pragma unroll 8
    for (int k = 0; k < 256; ++k) acc += ist[k] * wrow[k];
    (which ? g_s2 : g_s1)[b * 256 + c] = acc + 1.0f;
}

// ---------------- 3) demod (wsq fused inline) ----------------
__global__ void k_demod(const float* __restrict__ w1, const float* __restrict__ w2) {
    int o = blockIdx.x, b = blockIdx.y, which = blockIdx.z;
    int c = threadIdx.x;
    const float* w = (which ? w2 : w1) + ((size_t)o * 256 + c) * 9;
    const float* s = which ? g_s2 : g_s1;
    float wsq = 0.0f;
#pragma unroll
    for (int k = 0; k < 9; ++k) { float v = w[k]; wsq += v * v; }
    float sv = s[b * NC + c];
    float v = wsq * sv * sv;
    __shared__ float red[256];
    red[c] = v;
    __syncthreads();
    for (int st = 128; st; st >>= 1) {
        if (c < st) red[c] += red[c + st];
        __syncthreads();
    }
    if (c == 0) (which ? g_d2 : g_d1)[b * NO + o] = rsqrtf(red[0] + 1e-8f);
}

// ---------------- 4) weight prep directly in mma B-fragment layout ----------------
template <int MODE>
__global__ void k_prepfrag(const float* __restrict__ w, const float* __restrict__ w1x1) {
    constexpr int NT = (MODE == 0) ? 9 : 10;
    int bt = blockIdx.x;                   // b*NT + tap
    int ck = blockIdx.y;                   // 0..15
    int b = bt / NT, tap = bt % NT;
    int job = threadIdx.x;                 // 512: ntile*32 + lane
    int ntile = job >> 5, lane = job & 31;
    int n0 = ntile * 16 + (lane >> 2);
    int c0 = ck * 16 + 2 * (lane & 3);
    const float* s = (MODE == 0) ? g_s1 : g_s2;

    u32 o[4];
#pragma unroll
    for (int qn = 0; qn < 2; ++qn) {
#pragma unroll
        for (int qk = 0; qk < 2; ++qk) {
            int oc = n0 + qn * 8, c = c0 + qk * 8;
            float v0, v1;
            if (MODE == 1 && tap == 9) {
                float inv = 1.0f / g_d2[b * 256 + oc];
                v0 = w1x1[(size_t)oc * 256 + c] * inv;
                v1 = w1x1[(size_t)oc * 256 + c + 1] * inv;
            } else {
                v0 = w[((size_t)oc * 256 + c) * 9 + tap] * s[b * 256 + c];
                v1 = w[((size_t)oc * 256 + c + 1) * 9 + tap] * s[b * 256 + c + 1];
            }
            o[qn * 2 + qk] = (u32)__half_as_ushort(__float2half(v0))
                           | ((u32)__half_as_ushort(__float2half(v1)) << 16);
        }
    }
    size_t idx = (((size_t)bt * 16 + ck) * 16 + ntile) * 32 + lane;
    ((uint4*)(MODE == 0 ? g_Bf1 : g_Bf2))[idx] = make_uint4(o[0], o[1], o[2], o[3]);
}

// ---------------- 5) warp-MMA implicit-GEMM conv: A-halo tap reuse, n64 CTAs ----------------
// Stage = (dy, chunk): one 130-row halo A tile serves taps dy*3+{0,1,2} via ldsm row offset.
// MODE 0: 6 stages (src xh) -> y1 fp16 NHWC.
// MODE 1: 6 stages (src y1h) + 2 stages (src xh, tap 9 = folded 1x1 skip) -> out NCHW fp32.
// Per CTA: M=128 pixels x N=64 oc (quarter nh); 8 warps (2M x 4N), warp tile m64 x n16.
// Grid 2048 CTAs @ 2/SM -> 6.92 waves, ~1% drain quantization.
template <int MODE>
__global__ void __launch_bounds__(256, 2) k_convhmma(const float* __restrict__ bnoise,
                                                     float* __restrict__ outp) {
    constexpr int NT = (MODE == 0) ? 9 : 10;
    constexpr int SA = (MODE == 0) ? 6 : 8;
    extern __shared__ __align__(1024) char smem[];
    const u32 sb = smem_u32(smem);
    const int t = threadIdx.x;
    const int y0 = blockIdx.x, nh = blockIdx.y, b = blockIdx.z;
    const float* dmod = (MODE == 0) ? g_d1 : g_d2;
    const uint4* __restrict__ Bf = (const uint4*)((MODE == 0) ? g_Bf1 : g_Bf2);

    const int warp = t >> 5, lane = t & 31;
    const int wm = warp & 1, wn = warp >> 1;      // 2 m-tiles(64) x 4 n-tiles(16)
    const int li = lane >> 3, lr = lane & 7;

    // ldsm m-row base per m-tile (tile row = mbase + dxi, dxi in 0..2; tile row = x+1)
    int mbase[4];
#pragma unroll
    for (int mt = 0; mt < 4; ++mt)
        mbase[mt] = wm * 64 + mt * 16 + lr + ((li & 1) << 3);
    const u32 aCol = ((u32)li >> 1) << 4;

    float acc[4][2][4];
#pragma unroll
    for (int mt = 0; mt < 4; ++mt)
#pragma unroll
        for (int j = 0; j < 2; ++j)
#pragma unroll
            for (int q = 0; q < 4; ++q) acc[mt][j][q] = 0.0f;

    // Load halo A tile for stage sa: rows r=0..129 hold x = r-1 at y = y0 + ydel.
    auto load_stageA = [&](int sa) {
        int chunk, ydel;
        const __half* A;
        if (MODE == 1 && sa >= 6) { A = g_xh; ydel = 0; chunk = sa - 6; }
        else { A = (MODE == 0) ? g_xh : g_y1h; ydel = (sa >> 1) - 1; chunk = sa & 1; }
        int c0 = chunk << 7;
        u32 base = sb + (u32)(sa & 1) * STAGE_BYTES;
        int y = y0 + ydel;
        bool yok = ((unsigned)y < 128u);
        int yc = min(max(y, 0), 127);
        // 130 rows x 16 vec16 = 2080 cp16 ops
#pragma unroll
        for (int i = 0; i < 9; ++i) {
            int u = t + i * 256;
            if (u < 2080) {
                int r = u >> 4, j = u & 15;
                int xx = r - 1;
                bool ok = yok && ((unsigned)xx < 128u);
                int xc = min(max(xx, 0), 127);
                const __half* src = A + ((size_t)((b * 128 + yc) * 128 + xc) * 256 + c0 + j * 8);
                u32 dst = base + ((u32)r << 8) + ((((u32)j << 4)) ^ (((u32)r & 7u) << 4));
                cp16(dst, src, ok ? 16u : 0u);
            }
        }
        asm volatile("cp.async.commit_group;" ::: "memory");
    };

    load_stageA(0);
    asm volatile("cp.async.wait_group 0;" ::: "memory");
    __syncthreads();

    for (int sa = 0; sa < SA; ++sa) {
        const bool tap9 = (MODE == 1 && sa >= 6);
        const int chunk = tap9 ? (sa - 6) : (sa & 1);
        const int ndx = tap9 ? 1 : 3;
        const int tapbase = tap9 ? 9 : (sa >> 1) * 3;
        const int ckb = chunk * 8;

        if (sa + 1 < SA) load_stageA(sa + 1);

        const u32 abase = sb + (u32)(sa & 1) * STAGE_BYTES;
        for (int dxi = 0; dxi < ndx; ++dxi) {
            const int tap = tap9 ? 9 : (tapbase + dxi);
            const int rowoff = tap9 ? 1 : dxi;
            const size_t bbase =
                (((size_t)(b * NT + tap) * 16 + ckb) * 16 + nh * 4 + wn) * 32 + lane;

            // per-dx ldsm addressing
            u32 aR[4], aX[4];
#pragma unroll
            for (int mt = 0; mt < 4; ++mt) {
                int row = mbase[mt] + rowoff;
                aR[mt] = (u32)row << 8;
                aX[mt] = ((u32)row & 7u) << 4;
            }

            uint4 bq[2];
            bq[0] = __ldg(Bf + bbase);

#pragma unroll
            for (int kk = 0; kk < 8; ++kk) {
                if (kk < 7)
                    bq[(kk + 1) & 1] = __ldg(Bf + bbase + (size_t)(kk + 1) * 512);
                u32 ak = aCol + ((u32)kk << 5);
                u32 ah[4][4];
#pragma unroll
                for (int mt = 0; mt < 4; ++mt)
                    ldsm4(ah[mt], abase + aR[mt] + (ak ^ aX[mt]));
                uint4 q = bq[kk & 1];
#pragma unroll
                for (int mt = 0; mt < 4; ++mt) {
                    mma16816(acc[mt][0], ah[mt], q.x, q.y);
                    mma16816(acc[mt][1], ah[mt], q.z, q.w);
                }
            }
        }
        asm volatile("cp.async.wait_group 0;" ::: "memory");
        __syncthreads();
    }

    // ---------------- epilogue ----------------
    const int baseN = nh * 64 + wn * 16 + 2 * (lane & 3);
#pragma unroll
    for (int mt = 0; mt < 4; ++mt) {
#pragma unroll
        for (int h = 0; h < 2; ++h) {
            int m = wm * 64 + mt * 16 + (lane >> 2) + h * 8;
            if (MODE == 0) {
                size_t gi = ((size_t)(b * 128 + y0) * 128 + m) * 256;
#pragma unroll
                for (int j = 0; j < 2; ++j) {
                    int n = baseN + j * 8;
                    float r0 = acc[mt][j][h * 2]     * dmod[b * 256 + n]     + bnoise[n];
                    float r1 = acc[mt][j][h * 2 + 1] * dmod[b * 256 + n + 1] + bnoise[n + 1];
                    r0 = (r0 >= 0.0f) ? r0 : 0.2f * r0;
                    r1 = (r1 >= 0.0f) ? r1 : 0.2f * r1;
                    u32 h0 = (u32)__half_as_ushort(__float2half(r0));
                    u32 h1 = (u32)__half_as_ushort(__float2half(r1));
                    *(u32*)(g_y1h + gi + n) = h0 | (h1 << 16);
                }
            } else {
#pragma unroll
                for (int j = 0; j < 2; ++j) {
                    int n = baseN + j * 8;
                    float r0 = acc[mt][j][h * 2]     * dmod[b * 256 + n]     + bnoise[n];
                    float r1 = acc[mt][j][h * 2 + 1] * dmod[b * 256 + n + 1] + bnoise[n + 1];
                    r0 = (r0 >= 0.0f) ? r0 : 0.2f * r0;
                    r1 = (r1 >= 0.0f) ? r1 : 0.2f * r1;
                    outp[((size_t)(b * 256 + n)     * 128 + y0) * 128 + m] = r0;
                    outp[((size_t)(b * 256 + n + 1) * 128 + y0) * 128 + m] = r1;
                }
            }
        }
    }
}

// ---------------- launch ----------------
extern "C" void kernel_launch(void* const* d_in, const int* in_sizes, int n_in,
                              void* d_out, int out_size) {
    (void)in_sizes; (void)n_in; (void)out_size;
    const float* x         = (const float*)d_in[0];
    const float* istyle    = (const float*)d_in[1];
    const float* w_style1  = (const float*)d_in[2];
    const float* b_style1  = (const float*)d_in[3];
    const float* w_style2  = (const float*)d_in[4];
    const float* b_style2  = (const float*)d_in[5];
    const float* b_noise1  = (const float*)d_in[7];
    const float* b_noise2  = (const float*)d_in[9];
    const float* conv1_w   = (const float*)d_in[10];
    const float* conv2_w   = (const float*)d_in[11];
    const float* conv1x1_w = (const float*)d_in[12];
    float* out = (float*)d_out;

    cudaFuncSetAttribute(k_convhmma<0>, cudaFuncAttributeMaxDynamicSharedMemorySize, SMEM_BYTES);
    cudaFuncSetAttribute(k_convhmma<1>, cudaFuncAttributeMaxDynamicSharedMemorySize, SMEM_BYTES);

    k_upfuse<<<dim3(128, 4), 256>>>(x);
    k_styles<<<8, 256>>>(istyle, w_style1, b_style1, w_style2, b_style2);
    k_demod<<<dim3(256, 4, 2), 256>>>(conv1_w, conv2_w);
    k_prepfrag<0><<<dim3(36, 16), 512>>>(conv1_w, nullptr);
    k_prepfrag<1><<<dim3(40, 16), 512>>>(conv2_w, conv1x1_w);
    k_convhmma<0><<<dim3(128, 4, 4), 256, SMEM_BYTES>>>(b_noise1, nullptr);
    k_convhmma<1><<<dim3(128, 4, 4), 256, SMEM_BYTES>>>(b_noise2, out);
}

// round 17
// speedup vs baseline: 1.2114x; 1.2114x over previous
#include <cuda_runtime.h>
#include <cuda_fp16.h>
#include <cstdint>

typedef unsigned long long u64;
typedef unsigned int u32;

// ---------------- problem constants ----------------
constexpr int NB = 4, NC = 256, NO = 256;
constexpr int IH = 64, IW = 64, OH = 128, OW = 128;
constexpr size_t NELEM = (size_t)NB * NC * OH * OW;   // 16,777,216

// Stage buffer: A halo tile [130 rows (x-1..x+128)][128 c] fp16, pitch 256B = 33792 B.
constexpr u32 STAGE_BYTES = 33792;
constexpr u32 SMEM_BYTES = 2 * STAGE_BYTES;           // 67,584

// ---------------- device scratch ----------------
__device__ __align__(128) __half g_xh[NELEM];                // NHWC fp16 upsampled x
__device__ __align__(128) __half g_y1h[NELEM];               // NHWC fp16 y1
// B in mma fragment layout: [bt][ck(16)][ntile(16)][lane(32)] -> uint4
__device__ __align__(16) u32 g_Bf1[36 * 16 * 16 * 128];      // 1,179,648 u32
__device__ __align__(16) u32 g_Bf2[40 * 16 * 16 * 128];      // 1,310,720 u32
__device__ float g_s1[NB * NC], g_s2[NB * NC];
__device__ float g_d1[NB * NO], g_d2[NB * NO];

// ---------------- helpers ----------------
__device__ __forceinline__ u32 smem_u32(const void* p) {
    u32 a;
    asm("{ .reg .u64 t; cvta.to.shared.u64 t, %1; cvt.u32.u64 %0, t; }" : "=r"(a) : "l"(p));
    return a;
}
__device__ __forceinline__ void ldsm4(u32* r, u32 addr) {
    asm volatile("ldmatrix.sync.aligned.m8n8.x4.shared.b16 {%0,%1,%2,%3}, [%4];"
                 : "=r"(r[0]), "=r"(r[1]), "=r"(r[2]), "=r"(r[3]) : "r"(addr));
}
__device__ __forceinline__ void mma16816(float* d, const u32* a, u32 b0, u32 b1) {
    asm volatile("mma.sync.aligned.m16n8k16.row.col.f32.f16.f16.f32 "
                 "{%0,%1,%2,%3}, {%4,%5,%6,%7}, {%8,%9}, {%0,%1,%2,%3};"
                 : "+f"(d[0]), "+f"(d[1]), "+f"(d[2]), "+f"(d[3])
                 : "r"(a[0]), "r"(a[1]), "r"(a[2]), "r"(a[3]), "r"(b0), "r"(b1));
}
__device__ __forceinline__ void cp16(u32 dst, const void* src, u32 sz) {
    asm volatile("cp.async.cg.shared.global [%0], [%1], 16, %2;"
                 :: "r"(dst), "l"(src), "r"(sz) : "memory");
}

// ---------------- 1) fused NCHW fp32 -> bilinear 2x upsample -> NHWC fp16 ----------------
__global__ __launch_bounds__(256) void k_upfuse(const float* __restrict__ x) {
    __shared__ float tile[2][32][73];
    const int yo = blockIdx.x, b = blockIdx.y;
    const int t = threadIdx.x;

    int y0; float fy;
    if (yo & 1) { y0 = yo >> 1;       fy = 0.25f; }
    else        { y0 = (yo >> 1) - 1; fy = 0.75f; }
    const int y1c = min(y0 + 1, IH - 1);
    const int y0c = max(y0, 0);

    for (int c0 = 0; c0 < 256; c0 += 32) {
        __syncthreads();
#pragma unroll
        for (int k = 0; k < 16; ++k) {
            int idx = k * 256 + t;
            int xs = idx & 63, c = (idx >> 6) & 31, yq = idx >> 11;
            int ys = yq ? y1c : y0c;
            tile[yq][c][xs] = x[((size_t)(b * 256 + c0 + c) * 64 + ys) * 64 + xs];
        }
        __syncthreads();
#pragma unroll
        for (int k = 0; k < 8; ++k) {
            int pos = k * 256 + t;
            int c2 = pos & 15, xo = pos >> 4;
            int x0; float fx;
            if (xo & 1) { x0 = xo >> 1;       fx = 0.25f; }
            else        { x0 = (xo >> 1) - 1; fx = 0.75f; }
            int x1c = min(x0 + 1, IW - 1);
            int x0c = max(x0, 0);
            u32 outv = 0;
#pragma unroll
            for (int h = 0; h < 2; ++h) {
                int c = c2 * 2 + h;
                float v00 = tile[0][c][x0c], v01 = tile[0][c][x1c];
                float v10 = tile[1][c][x0c], v11 = tile[1][c][x1c];
                float vt = v00 + fx * (v01 - v00);
                float vb = v10 + fx * (v11 - v10);
                u32 hb = (u32)__half_as_ushort(__float2half(vt + fy * (vb - vt)));
                outv |= hb << (16 * h);
            }
            *(u32*)(g_xh + ((size_t)(b * 128 + yo) * 128 + xo) * 256 + c0 + c2 * 2) = outv;
        }
    }
}

// ---------------- 2) styles ----------------
__global__ void k_styles(const float* __restrict__ istyle,
                         const float* __restrict__ w1, const float* __restrict__ b1,
                         const float* __restrict__ w2, const float* __restrict__ b2) {
    int b = blockIdx.x & 3;
    int which = blockIdx.x >> 2;
    int c = threadIdx.x;
    const float* wrow = (which ? w2 : w1) + (size_t)c * 256;
    const float* ist = istyle + b * 256;
    float acc = (which ? b2 : b1)[c];
#pragma unroll 8
    for (int k = 0; k < 256; ++k) acc += ist[k] * wrow[k];
    (which ? g_s2 : g_s1)[b * 256 + c] = acc + 1.0f;
}

// ---------------- 3) demod (wsq fused inline) ----------------
__global__ void k_demod(const float* __restrict__ w1, const float* __restrict__ w2) {
    int o = blockIdx.x, b = blockIdx.y, which = blockIdx.z;
    int c = threadIdx.x;
    const float* w = (which ? w2 : w1) + ((size_t)o * 256 + c) * 9;
    const float* s = which ? g_s2 : g_s1;
    float wsq = 0.0f;
#pragma unroll
    for (int k = 0; k < 9; ++k) { float v = w[k]; wsq += v * v; }
    float sv = s[b * NC + c];
    float v = wsq * sv * sv;
    __shared__ float red[256];
    red[c] = v;
    __syncthreads();
    for (int st = 128; st; st >>= 1) {
        if (c < st) red[c] += red[c + st];
        __syncthreads();
    }
    if (c == 0) (which ? g_d2 : g_d1)[b * NO + o] = rsqrtf(red[0] + 1e-8f);
}

// ---------------- 4) weight prep in mma B-fragment layout, all 4 batches/block ----------
// Fragment: for (bt, ck, ntile, lane): n0 = ntile*16 + (lane>>2), c0 = ck*16 + 2*(lane&3):
//   u32[q] = half2 over (n0 + 8*(q>>1), c0 + 8*(q&1)) pairs.
// W is batch-independent: read once, scale by per-batch style (or demod for tap9).
template <int MODE>
__global__ void k_prepfrag(const float* __restrict__ w, const float* __restrict__ w1x1) {
    constexpr int NT = (MODE == 0) ? 9 : 10;
    int tap = blockIdx.x;                  // 0..NT-1
    int ck = blockIdx.y;                   // 0..15
    int job = threadIdx.x;                 // 512: ntile*32 + lane
    int ntile = job >> 5, lane = job & 31;
    int n0 = ntile * 16 + (lane >> 2);
    int c0 = ck * 16 + 2 * (lane & 3);
    const float* s = (MODE == 0) ? g_s1 : g_s2;
    const bool t9 = (MODE == 1 && tap == 9);

    // batch-independent weight reads (8 scalars, once)
    float wv[2][2][2];                     // [qn][qk][pair]
#pragma unroll
    for (int qn = 0; qn < 2; ++qn)
#pragma unroll
        for (int qk = 0; qk < 2; ++qk) {
            int oc = n0 + qn * 8, c = c0 + qk * 8;
            if (t9) {
                wv[qn][qk][0] = w1x1[(size_t)oc * 256 + c];
                wv[qn][qk][1] = w1x1[(size_t)oc * 256 + c + 1];
            } else {
                wv[qn][qk][0] = w[((size_t)oc * 256 + c) * 9 + tap];
                wv[qn][qk][1] = w[((size_t)oc * 256 + c + 1) * 9 + tap];
            }
        }

    uint4* dst = (uint4*)(MODE == 0 ? g_Bf1 : g_Bf2);
#pragma unroll
    for (int b = 0; b < 4; ++b) {
        u32 o[4];
#pragma unroll
        for (int qn = 0; qn < 2; ++qn)
#pragma unroll
            for (int qk = 0; qk < 2; ++qk) {
                int oc = n0 + qn * 8, c = c0 + qk * 8;
                float f0, f1;
                if (t9) {
                    float inv = 1.0f / g_d2[b * 256 + oc];
                    f0 = wv[qn][qk][0] * inv;
                    f1 = wv[qn][qk][1] * inv;
                } else {
                    f0 = wv[qn][qk][0] * s[b * 256 + c];
                    f1 = wv[qn][qk][1] * s[b * 256 + c + 1];
                }
                o[qn * 2 + qk] = (u32)__half_as_ushort(__float2half(f0))
                               | ((u32)__half_as_ushort(__float2half(f1)) << 16);
            }
        size_t idx = ((((size_t)(b * NT + tap)) * 16 + ck) * 16 + ntile) * 32 + lane;
        dst[idx] = make_uint4(o[0], o[1], o[2], o[3]);
    }
}

// ---------------- 5) warp-MMA implicit-GEMM conv with A-halo tap reuse (R15) ----------
// Stage = (dy, chunk): one 130-row halo A tile serves taps dy*3+{0,1,2} via ldsm row offset.
// MODE 0: 6 stages (src xh) -> y1 fp16 NHWC.
// MODE 1: 6 stages (src y1h) + 2 stages (src xh, tap 9 = folded 1x1 skip) -> out NCHW fp32.
// Per CTA: M=128 pixels x N=128 oc; 8 warps (2M x 4N), warp tile m64 x n32; 2 CTAs/SM.
template <int MODE>
__global__ void __launch_bounds__(256, 2) k_convhmma(const float* __restrict__ bnoise,
                                                     float* __restrict__ outp) {
    constexpr int NT = (MODE == 0) ? 9 : 10;
    constexpr int SA = (MODE == 0) ? 6 : 8;
    extern __shared__ __align__(1024) char smem[];
    const u32 sb = smem_u32(smem);
    const int t = threadIdx.x;
    const int y0 = blockIdx.x, nh = blockIdx.y, b = blockIdx.z;
    const float* dmod = (MODE == 0) ? g_d1 : g_d2;
    const uint4* __restrict__ Bf = (const uint4*)((MODE == 0) ? g_Bf1 : g_Bf2);

    const int warp = t >> 5, lane = t & 31;
    const int wm = warp & 1, wn = warp >> 1;      // 2 m-tiles(64) x 4 n-tiles(32)
    const int li = lane >> 3, lr = lane & 7;

    int mbase[4];
#pragma unroll
    for (int mt = 0; mt < 4; ++mt)
        mbase[mt] = wm * 64 + mt * 16 + lr + ((li & 1) << 3);
    const u32 aCol = ((u32)li >> 1) << 4;

    float acc[4][4][4];
#pragma unroll
    for (int mt = 0; mt < 4; ++mt)
#pragma unroll
        for (int j = 0; j < 4; ++j)
#pragma unroll
            for (int q = 0; q < 4; ++q) acc[mt][j][q] = 0.0f;

    auto load_stageA = [&](int sa) {
        int chunk, ydel;
        const __half* A;
        if (MODE == 1 && sa >= 6) { A = g_xh; ydel = 0; chunk = sa - 6; }
        else { A = (MODE == 0) ? g_xh : g_y1h; ydel = (sa >> 1) - 1; chunk = sa & 1; }
        int c0 = chunk << 7;
        u32 base = sb + (u32)(sa & 1) * STAGE_BYTES;
        int y = y0 + ydel;
        bool yok = ((unsigned)y < 128u);
        int yc = min(max(y, 0), 127);
#pragma unroll
        for (int i = 0; i < 9; ++i) {
            int u = t + i * 256;
            if (u < 2080) {
                int r = u >> 4, j = u & 15;
                int xx = r - 1;
                bool ok = yok && ((unsigned)xx < 128u);
                int xc = min(max(xx, 0), 127);
                const __half* src = A + ((size_t)((b * 128 + yc) * 128 + xc) * 256 + c0 + j * 8);
                u32 dst = base + ((u32)r << 8) + ((((u32)j << 4)) ^ (((u32)r & 7u) << 4));
                cp16(dst, src, ok ? 16u : 0u);
            }
        }
        asm volatile("cp.async.commit_group;" ::: "memory");
    };

    load_stageA(0);
    asm volatile("cp.async.wait_group 0;" ::: "memory");
    __syncthreads();

    for (int sa = 0; sa < SA; ++sa) {
        const bool tap9 = (MODE == 1 && sa >= 6);
        const int chunk = tap9 ? (sa - 6) : (sa & 1);
        const int ndx = tap9 ? 1 : 3;
        const int tapbase = tap9 ? 9 : (sa >> 1) * 3;
        const int ckb = chunk * 8;

        if (sa + 1 < SA) load_stageA(sa + 1);

        const u32 abase = sb + (u32)(sa & 1) * STAGE_BYTES;
        for (int dxi = 0; dxi < ndx; ++dxi) {
            const int tap = tap9 ? 9 : (tapbase + dxi);
            const int rowoff = tap9 ? 1 : dxi;
            const size_t bbase =
                (((size_t)(b * NT + tap) * 16 + ckb) * 16 + nh * 8 + wn * 2) * 32 + lane;

            u32 aR[4], aX[4];
#pragma unroll
            for (int mt = 0; mt < 4; ++mt) {
                int row = mbase[mt] + rowoff;
                aR[mt] = (u32)row << 8;
                aX[mt] = ((u32)row & 7u) << 4;
            }

            uint4 bq[2][2];
#pragma unroll
            for (int p = 0; p < 2; ++p) bq[0][p] = __ldg(Bf + bbase + p * 32);

#pragma unroll
            for (int kk = 0; kk < 8; ++kk) {
                if (kk < 7) {
#pragma unroll
                    for (int p = 0; p < 2; ++p)
                        bq[(kk + 1) & 1][p] = __ldg(Bf + bbase + (size_t)(kk + 1) * 512 + p * 32);
                }
                u32 ak = aCol + ((u32)kk << 5);
                u32 ah[4][4];
#pragma unroll
                for (int mt = 0; mt < 4; ++mt)
                    ldsm4(ah[mt], abase + aR[mt] + (ak ^ aX[mt]));
#pragma unroll
                for (int p = 0; p < 2; ++p) {
                    uint4 q = bq[kk & 1][p];
#pragma unroll
                    for (int mt = 0; mt < 4; ++mt) {
                        mma16816(acc[mt][2 * p],     ah[mt], q.x, q.y);
                        mma16816(acc[mt][2 * p + 1], ah[mt], q.z, q.w);
                    }
                }
            }
        }
        asm volatile("cp.async.wait_group 0;" ::: "memory");
        __syncthreads();
    }

    // ---------------- epilogue ----------------
    const int baseN = nh * 128 + wn * 32 + 2 * (lane & 3);
#pragma unroll
    for (int mt = 0; mt < 4; ++mt) {
#pragma unroll
        for (int h = 0; h < 2; ++h) {
            int m = wm * 64 + mt * 16 + (lane >> 2) + h * 8;
            if (MODE == 0) {
                size_t gi = ((size_t)(b * 128 + y0) * 128 + m) * 256;
#pragma unroll
                for (int j = 0; j < 4; ++j) {
                    int n = baseN + j * 8;
                    float r0 = acc[mt][j][h * 2]     * dmod[b * 256 + n]     + bnoise[n];
                    float r1 = acc[mt][j][h * 2 + 1] * dmod[b * 256 + n + 1] + bnoise[n + 1];
                    r0 = (r0 >= 0.0f) ? r0 : 0.2f * r0;
                    r1 = (r1 >= 0.0f) ? r1 : 0.2f * r1;
                    u32 h0 = (u32)__half_as_ushort(__float2half(r0));
                    u32 h1 = (u32)__half_as_ushort(__float2half(r1));
                    *(u32*)(g_y1h + gi + n) = h0 | (h1 << 16);
                }
            } else {
#pragma unroll
                for (int j = 0; j < 4; ++j) {
                    int n = baseN + j * 8;
                    float r0 = acc[mt][j][h * 2]     * dmod[b * 256 + n]     + bnoise[n];
                    float r1 = acc[mt][j][h * 2 + 1] * dmod[b * 256 + n + 1] + bnoise[n + 1];
                    r0 = (r0 >= 0.0f) ? r0 : 0.2f * r0;
                    r1 = (r1 >= 0.0f) ? r1 : 0.2f * r1;
                    outp[((size_t)(b * 256 + n)     * 128 + y0) * 128 + m] = r0;
                    outp[((size_t)(b * 256 + n + 1) * 128 + y0) * 128 + m] = r1;
                }
            }
        }
    }
}

// ---------------- launch ----------------
extern "C" void kernel_launch(void* const* d_in, const int* in_sizes, int n_in,
                              void* d_out, int out_size) {
    (void)in_sizes; (void)n_in; (void)out_size;
    const float* x         = (const float*)d_in[0];
    const float* istyle    = (const float*)d_in[1];
    const float* w_style1  = (const float*)d_in[2];
    const float* b_style1  = (const float*)d_in[3];
    const float* w_style2  = (const float*)d_in[4];
    const float* b_style2  = (const float*)d_in[5];
    const float* b_noise1  = (const float*)d_in[7];
    const float* b_noise2  = (const float*)d_in[9];
    const float* conv1_w   = (const float*)d_in[10];
    const float* conv2_w   = (const float*)d_in[11];
    const float* conv1x1_w = (const float*)d_in[12];
    float* out = (float*)d_out;

    cudaFuncSetAttribute(k_convhmma<0>, cudaFuncAttributeMaxDynamicSharedMemorySize, SMEM_BYTES);
    cudaFuncSetAttribute(k_convhmma<1>, cudaFuncAttributeMaxDynamicSharedMemorySize, SMEM_BYTES);

    k_upfuse<<<dim3(128, 4), 256>>>(x);
    k_styles<<<8, 256>>>(istyle, w_style1, b_style1, w_style2, b_style2);
    k_demod<<<dim3(256, 4, 2), 256>>>(conv1_w, conv2_w);
    k_prepfrag<0><<<dim3(9, 16), 512>>>(conv1_w, nullptr);
    k_prepfrag<1><<<dim3(10, 16), 512>>>(conv2_w, conv1x1_w);
    k_convhmma<0><<<dim3(128, 2, 4), 256, SMEM_BYTES>>>(b_noise1, nullptr);
    k_convhmma<1><<<dim3(128, 2, 4), 256, SMEM_BYTES>>>(b_noise2, out);
}